// round 1
// baseline (speedup 1.0000x reference)
#include <cuda_runtime.h>

#define H_IN 512
#define W_IN 512
#define H_OUT 512
#define W_OUT 512
#define BC 96            // 32 batch * 3 channels
#define HW (H_IN * W_IN) // 262144

// max_r = log(sqrt(512^2+512^2)/2 * 2) = log(512*sqrt(2)) = 6.58489821532...
#define MAX_R 6.58489821532f
#define PI_F 3.14159265358979f

__global__ __launch_bounds__(256) void logpolar_kernel(
    const float* __restrict__ in, float* __restrict__ out)
{
    int pix = blockIdx.x * blockDim.x + threadIdx.x;
    if (pix >= HW) return;

    int i = pix >> 9;    // theta index (row of output)
    int j = pix & 511;   // r index (col of output)

    // radius = exp(j * max_r / W_OUT)   (division by 512 is exact)
    float rv = (float)j * MAX_R / (float)W_OUT;
    float radius = expf(rv);

    // ang = theta * 2 * pi / H_OUT  -> ((2*i) * pi) / 512
    float ang = (float)(2 * i) * PI_F / (float)H_OUT;
    float s, c;
    sincosf(ang, &s, &c);

    float X = 256.0f + radius * c;   // center_x + X0
    float Y = 256.0f - radius * s;   // center_y - Y0

    float mask = (X >= 0.0f && X < (float)H_IN && Y >= 0.0f && Y < (float)W_IN)
                     ? 1.0f : 0.0f;

    // trunc toward zero (matches astype(int32)), then clamp
    int ydi = (int)Y;  ydi = min(max(ydi, 0), H_IN - 1);
    int xdi = (int)X;  xdi = min(max(xdi, 0), W_IN - 1);
    int yui = min(ydi + 1, H_IN - 1);
    int xui = min(xdi + 1, W_IN - 1);

    float yd = Y - (float)ydi;
    float yu = Y - (float)yui;
    float xd = X - (float)xdi;
    float xu = X - (float)xui;

    float yd2 = yd * yd, yu2 = yu * yu, xd2 = xd * xd, xu2 = xu * xu;
    float dd = yd2 + xd2;
    float du = yd2 + xu2;
    float ud = yu2 + xd2;
    float uu = yu2 + xu2;
    float total = dd + du + ud + uu;
    float inv = mask / total;   // fold mask into weights

    float wdd = dd * inv;
    float wdu = du * inv;
    float wud = ud * inv;
    float wuu = uu * inv;

    int o_dd = ydi * W_IN + xdi;
    int o_du = ydi * W_IN + xui;
    int o_ud = yui * W_IN + xdi;
    int o_uu = yui * W_IN + xui;

    const float* src = in;
    float* dst = out + pix;

#pragma unroll 4
    for (int bc = 0; bc < BC; ++bc) {
        float vdd = __ldg(src + o_dd);
        float vdu = __ldg(src + o_du);
        float vud = __ldg(src + o_ud);
        float vuu = __ldg(src + o_uu);
        float r = wdd * vdd + wdu * vdu + wud * vud + wuu * vuu;
        dst[(size_t)bc * HW] = r;
        src += HW;
    }
}

extern "C" void kernel_launch(void* const* d_in, const int* in_sizes, int n_in,
                              void* d_out, int out_size)
{
    const float* in = (const float*)d_in[0];
    float* out = (float*)d_out;
    int threads = 256;
    int blocks = (HW + threads - 1) / threads;
    logpolar_kernel<<<blocks, threads>>>(in, out);
}

// round 2
// speedup vs baseline: 1.6280x; 1.6280x over previous
#include <cuda_runtime.h>

#define H_IN 512
#define W_IN 512
#define H_OUT 512
#define W_OUT 512
#define BC 96            // 32 batch * 3 channels
#define HW (H_IN * W_IN) // 262144
#define BC_CHUNK 16
#define NCHUNK (BC / BC_CHUNK)   // 6

// max_r = log(sqrt(512^2+512^2)/2 * 2) = log(512*sqrt(2))
#define MAX_R 6.58489821532f
#define PI_F 3.14159265358979f

// Precomputed map: weights (mask folded in) and the two row-tap offsets.
__device__ float4 g_w[HW];   // wdd, wdu, wud, wuu
__device__ int2   g_o[HW];   // o_dd (= ydi*512+xdi), o_ud (= yui*512+xdi)

__global__ __launch_bounds__(256) void map_kernel()
{
    int pix = blockIdx.x * blockDim.x + threadIdx.x;
    if (pix >= HW) return;

    int i = pix >> 9;    // theta index
    int j = pix & 511;   // r index

    float rv = (float)j * MAX_R / (float)W_OUT;
    float radius = expf(rv);

    float ang = (float)(2 * i) * PI_F / (float)H_OUT;
    float s, c;
    sincosf(ang, &s, &c);

    float X = 256.0f + radius * c;
    float Y = 256.0f - radius * s;

    float mask = (X >= 0.0f && X < (float)H_IN && Y >= 0.0f && Y < (float)W_IN)
                     ? 1.0f : 0.0f;

    int ydi = (int)Y;  ydi = min(max(ydi, 0), H_IN - 1);
    int xdi = (int)X;  xdi = min(max(xdi, 0), W_IN - 1);
    int yui = min(ydi + 1, H_IN - 1);
    int xui = min(xdi + 1, W_IN - 1);

    float yd = Y - (float)ydi;
    float yu = Y - (float)yui;
    float xd = X - (float)xdi;
    float xu = X - (float)xui;

    float yd2 = yd * yd, yu2 = yu * yu, xd2 = xd * xd, xu2 = xu * xu;
    float dd = yd2 + xd2;
    float du = yd2 + xu2;
    float ud = yu2 + xd2;
    float uu = yu2 + xu2;
    float total = dd + du + ud + uu;
    float inv = mask / total;

    g_w[pix] = make_float4(dd * inv, du * inv, ud * inv, uu * inv);
    g_o[pix] = make_int2(ydi * W_IN + xdi, yui * W_IN + xdi);
}

__global__ __launch_bounds__(128, 8) void gather_kernel(
    const float* __restrict__ in, float* __restrict__ out)
{
    int pix = blockIdx.x * 128 + threadIdx.x;
    int bc0 = blockIdx.y * BC_CHUNK;

    float4 w = g_w[pix];
    int2 o = g_o[pix];

    int sel   = o.x & 3;
    int base_d = o.x & ~3;
    int base_u = o.y & ~3;
    int xdi   = o.x & 511;
    int d1    = (xdi < W_IN - 1) ? 1 : 0;
    int o_du  = o.x + d1;
    int o_uu  = o.y + d1;

    bool s1 = (sel == 1), s2 = (sel == 2), s3 = (sel == 3);

    const float* src = in + (size_t)bc0 * HW;
    float* dst = out + (size_t)bc0 * HW + pix;

#pragma unroll 4
    for (int k = 0; k < BC_CHUNK; ++k) {
        float4 fd = __ldg(reinterpret_cast<const float4*>(src + base_d));
        float4 fu = __ldg(reinterpret_cast<const float4*>(src + base_u));

        float sdu = 0.0f, suu = 0.0f;
        if (s3) {
            sdu = __ldg(src + o_du);
            suu = __ldg(src + o_uu);
        }

        float vdd = s1 ? fd.y : fd.x;  vdd = s2 ? fd.z : vdd;  vdd = s3 ? fd.w : vdd;
        float vud = s1 ? fu.y : fu.x;  vud = s2 ? fu.z : vud;  vud = s3 ? fu.w : vud;
        float vdu = s1 ? fd.z : fd.y;  vdu = s2 ? fd.w : vdu;  vdu = s3 ? sdu  : vdu;
        float vuu = s1 ? fu.z : fu.y;  vuu = s2 ? fu.w : vuu;  vuu = s3 ? suu  : vuu;

        float r = w.x * vdd + w.y * vdu + w.z * vud + w.w * vuu;
        *dst = r;

        src += HW;
        dst += HW;
    }
}

extern "C" void kernel_launch(void* const* d_in, const int* in_sizes, int n_in,
                              void* d_out, int out_size)
{
    const float* in = (const float*)d_in[0];
    float* out = (float*)d_out;

    map_kernel<<<HW / 256, 256>>>();

    dim3 grid(HW / 128, NCHUNK);
    gather_kernel<<<grid, 128>>>(in, out);
}